// round 2
// baseline (speedup 1.0000x reference)
#include <cuda_runtime.h>
#include <cuda_bf16.h>
#include <math.h>

#define NN 50000
#define NE 800000
#define NG 256
#define INF 128
#define H 64
#define BN_EPS 1e-5f

// ------------------------ device scratch (no allocs allowed) -----------------
__device__ int   g_flag;            // 1 if indices are int64, 0 if int32
__device__ int   g_src[NE];
__device__ int   g_dst[NE];
__device__ int   g_batch[NN];
__device__ int   g_cnt[NN];
__device__ int   g_rowstart[NN + 1];
__device__ int   g_cursor[NN];
__device__ float g_invcnt[NN];
__device__ int   g_csr_src[NE];
__device__ float g_y[NN * H];
__device__ float g_aggn[NN * H];
__device__ float g_hA[NN * H];
__device__ float g_hB[NN * H];
__device__ float g_pool[NG * H];
__device__ float g_pcnt[NG];
__device__ float g_t1[NG * 256];
__device__ float g_t2[NG * 128];
__device__ float g_t3[NG * 64];

// ------------------------ dtype probe ---------------------------------------
__global__ void detect_kernel(const long long* ei, const long long* bt) {
    __shared__ int bad;
    if (threadIdx.x == 0) bad = 0;
    __syncthreads();
    long long v = ei[threadIdx.x];
    if (v < 0 || v >= NN) bad = 1;
    long long b = bt[threadIdx.x];
    if (b < 0 || b >= NG) bad = 1;
    __syncthreads();
    if (threadIdx.x == 0) g_flag = bad ? 0 : 1;
}

__global__ void convert_kernel(const void* ei, const void* bt) {
    int i = blockIdx.x * blockDim.x + threadIdx.x;
    bool is64 = (g_flag != 0);
    if (i < NE) {
        if (is64) {
            const long long* p = (const long long*)ei;
            g_src[i] = (int)p[i];
            g_dst[i] = (int)p[NE + i];
        } else {
            const int* p = (const int*)ei;
            g_src[i] = p[i];
            g_dst[i] = p[NE + i];
        }
    }
    if (i < NN) {
        if (is64) g_batch[i] = (int)((const long long*)bt)[i];
        else      g_batch[i] = ((const int*)bt)[i];
    }
}

// ------------------------ CSR build -----------------------------------------
__global__ void zero_cnt_kernel() {
    int i = blockIdx.x * blockDim.x + threadIdx.x;
    if (i < NN) g_cnt[i] = 0;
}

__global__ void hist_kernel() {
    int e = blockIdx.x * blockDim.x + threadIdx.x;
    if (e < NE) atomicAdd(&g_cnt[g_dst[e]], 1);
}

__global__ void scan_kernel() {
    __shared__ int s[1024];
    __shared__ int carry;
    int tid = threadIdx.x;
    if (tid == 0) carry = 0;
    __syncthreads();
    for (int base = 0; base < NN; base += 1024) {
        int v = (base + tid < NN) ? g_cnt[base + tid] : 0;
        s[tid] = v;
        __syncthreads();
        for (int off = 1; off < 1024; off <<= 1) {
            int t = (tid >= off) ? s[tid - off] : 0;
            __syncthreads();
            s[tid] += t;
            __syncthreads();
        }
        int excl = s[tid] - v;
        if (base + tid < NN) {
            int rs = carry + excl;
            g_rowstart[base + tid] = rs;
            g_cursor[base + tid] = rs;
            g_invcnt[base + tid] = 1.0f / (float)max(v, 1);
        }
        __syncthreads();
        if (tid == 1023) carry += s[1023];
        __syncthreads();
    }
    if (tid == 0) g_rowstart[NN] = carry;
}

__global__ void fill_kernel() {
    int e = blockIdx.x * blockDim.x + threadIdx.x;
    if (e < NE) {
        int d = g_dst[e];
        int pos = atomicAdd(&g_cursor[d], 1);
        g_csr_src[pos] = g_src[e];
    }
}

// ------------------------ tall-skinny GEMM (M x K) @ (K x 64) ---------------
// EPI: C = A@W + bias + g_aggn  (SAGE combine). Otherwise C = A@W.
template <int K, bool EPI>
__global__ void gemm_conv(const float* __restrict__ A, const float* __restrict__ W,
                          const float* __restrict__ bias, float* __restrict__ C) {
    __shared__ float As[128 * 33];   // padded: stride 33 avoids bank conflicts
    __shared__ float Ws[32 * 64];
    int m0 = blockIdx.x * 128;
    int tid = threadIdx.x;           // 256 threads
    int rg = tid >> 4;               // 16 row groups * 8 rows
    int cg = tid & 15;               // 16 col groups * 4 cols

    float acc[8][4];
#pragma unroll
    for (int r = 0; r < 8; r++)
#pragma unroll
        for (int c = 0; c < 4; c++) acc[r][c] = 0.f;

    for (int k0 = 0; k0 < K; k0 += 32) {
#pragma unroll
        for (int i = 0; i < 16; i++) {
            int idx = i * 256 + tid;
            int r = idx >> 5, c = idx & 31;
            int gr = m0 + r;
            As[r * 33 + c] = (gr < NN) ? A[gr * K + k0 + c] : 0.f;
        }
#pragma unroll
        for (int i = 0; i < 8; i++) {
            int idx = i * 256 + tid;
            int r = idx >> 6, c = idx & 63;
            Ws[idx] = W[(k0 + r) * 64 + c];
        }
        __syncthreads();
#pragma unroll
        for (int k = 0; k < 32; k++) {
            float a[8], w[4];
#pragma unroll
            for (int r = 0; r < 8; r++) a[r] = As[(rg * 8 + r) * 33 + k];
            float4 wv = *(const float4*)&Ws[k * 64 + cg * 4];
            w[0] = wv.x; w[1] = wv.y; w[2] = wv.z; w[3] = wv.w;
#pragma unroll
            for (int r = 0; r < 8; r++)
#pragma unroll
                for (int c = 0; c < 4; c++) acc[r][c] = fmaf(a[r], w[c], acc[r][c]);
        }
        __syncthreads();
    }

#pragma unroll
    for (int r = 0; r < 8; r++) {
        int gr = m0 + rg * 8 + r;
        if (gr < NN) {
            float4 v;
            v.x = acc[r][0]; v.y = acc[r][1]; v.z = acc[r][2]; v.w = acc[r][3];
            if (EPI) {
                int col = cg * 4;
                float4 ag = *(const float4*)&g_aggn[gr * 64 + col];
                v.x += bias[col + 0] + ag.x;
                v.y += bias[col + 1] + ag.y;
                v.z += bias[col + 2] + ag.z;
                v.w += bias[col + 3] + ag.w;
            }
            *(float4*)&C[gr * 64 + cg * 4] = v;
        }
    }
}

// ------------------------ edge aggregation (warp per dst node) --------------
__global__ void aggregate_kernel() {
    int w = (blockIdx.x * blockDim.x + threadIdx.x) >> 5;
    int lane = threadIdx.x & 31;
    if (w >= NN) return;
    int s0 = g_rowstart[w], s1 = g_rowstart[w + 1];
    float ax = 0.f, ay = 0.f;
    for (int k = s0; k < s1; k++) {
        int s = g_csr_src[k];
        float2 v = *(const float2*)&g_y[s * 64 + lane * 2];
        ax += v.x; ay += v.y;
    }
    float ic = g_invcnt[w];
    float2 o; o.x = ax * ic; o.y = ay * ic;
    *(float2*)&g_aggn[w * 64 + lane * 2] = o;
}

// ------------------------ pooling -------------------------------------------
__global__ void zero_pool_kernel() {
    int i = blockIdx.x * blockDim.x + threadIdx.x;
    if (i < NG * H) g_pool[i] = 0.f;
    if (i < NG) g_pcnt[i] = 0.f;
}

__global__ void pool_kernel() {
    int w = (blockIdx.x * blockDim.x + threadIdx.x) >> 5;
    int lane = threadIdx.x & 31;
    if (w >= NN) return;
    int g = g_batch[w];
    float2 v = *(const float2*)&g_hA[w * 64 + lane * 2];
    atomicAdd(&g_pool[g * 64 + lane * 2 + 0], v.x);
    atomicAdd(&g_pool[g * 64 + lane * 2 + 1], v.y);
    if (lane == 0) atomicAdd(&g_pcnt[g], 1.f);
}

__global__ void poolnorm_kernel() {
    int i = blockIdx.x * blockDim.x + threadIdx.x;
    if (i < NG * H) {
        float c = g_pcnt[i >> 6];
        g_pool[i] = g_pool[i] / fmaxf(c, 1.f);
    }
}

// ------------------------ small MLP GEMM + BN -------------------------------
__global__ void gemm_small(const float* __restrict__ A, const float* __restrict__ W,
                           const float* __restrict__ b, float* __restrict__ C,
                           int N, int K) {
    int j = blockIdx.x * blockDim.x + threadIdx.x;
    int i = blockIdx.y;
    if (j >= N) return;
    float acc = b[j];
    for (int k = 0; k < K; k++) acc = fmaf(A[i * K + k], W[k * N + j], acc);
    C[i * N + j] = acc;
}

__global__ void bn_tanh_kernel(float* __restrict__ X, const float* __restrict__ gam,
                               const float* __restrict__ bet, int N) {
    int j = blockIdx.x, i = threadIdx.x;   // 256 rows
    __shared__ float red[256];
    float v = X[i * N + j];
    red[i] = v;
    __syncthreads();
    for (int off = 128; off > 0; off >>= 1) {
        if (i < off) red[i] += red[i + off];
        __syncthreads();
    }
    float mean = red[0] / 256.f;
    __syncthreads();
    float d = v - mean;
    red[i] = d * d;
    __syncthreads();
    for (int off = 128; off > 0; off >>= 1) {
        if (i < off) red[i] += red[i + off];
        __syncthreads();
    }
    float var = red[0] / 256.f;
    X[i * N + j] = tanhf(d * rsqrtf(var + BN_EPS) * gam[j] + bet[j]);
}

// ------------------------ launch --------------------------------------------
extern "C" void kernel_launch(void* const* d_in, const int* in_sizes, int n_in,
                              void* d_out, int out_size) {
    const float* x      = (const float*)d_in[0];
    const void*  ei     = d_in[1];
    const void*  bt     = d_in[2];
    const float* W1l    = (const float*)d_in[3];
    const float* b1l    = (const float*)d_in[4];
    const float* W1r    = (const float*)d_in[5];
    const float* W2l    = (const float*)d_in[6];
    const float* b2l    = (const float*)d_in[7];
    const float* W2r    = (const float*)d_in[8];
    const float* W3l    = (const float*)d_in[9];
    const float* b3l    = (const float*)d_in[10];
    const float* W3r    = (const float*)d_in[11];
    const float* lin1_w = (const float*)d_in[12];
    const float* lin1_b = (const float*)d_in[13];
    const float* g1     = (const float*)d_in[14];
    const float* be1    = (const float*)d_in[15];
    const float* lin2_w = (const float*)d_in[16];
    const float* lin2_b = (const float*)d_in[17];
    const float* g2     = (const float*)d_in[18];
    const float* be2    = (const float*)d_in[19];
    const float* lin3_w = (const float*)d_in[20];
    const float* lin3_b = (const float*)d_in[21];
    const float* g3     = (const float*)d_in[22];
    const float* be3    = (const float*)d_in[23];
    const float* lin4_w = (const float*)d_in[24];
    const float* lin4_b = (const float*)d_in[25];
    float* out = (float*)d_out;

    float *pY, *pHA, *pHB, *pPool, *pT1, *pT2, *pT3;
    cudaGetSymbolAddress((void**)&pY,    g_y);
    cudaGetSymbolAddress((void**)&pHA,   g_hA);
    cudaGetSymbolAddress((void**)&pHB,   g_hB);
    cudaGetSymbolAddress((void**)&pPool, g_pool);
    cudaGetSymbolAddress((void**)&pT1,   g_t1);
    cudaGetSymbolAddress((void**)&pT2,   g_t2);
    cudaGetSymbolAddress((void**)&pT3,   g_t3);

    const int EB = (NE + 255) / 256;          // 3125
    const int MB = (NN + 127) / 128;          // 391
    const int WB = (NN * 32 + 255) / 256;     // 6250

    detect_kernel<<<1, 256>>>((const long long*)ei, (const long long*)bt);
    convert_kernel<<<EB, 256>>>(ei, bt);
    zero_cnt_kernel<<<(NN + 255) / 256, 256>>>();
    hist_kernel<<<EB, 256>>>();
    scan_kernel<<<1, 1024>>>();
    fill_kernel<<<EB, 256>>>();

    // ---- layer 1: in = x (K=128) ----
    gemm_conv<128, false><<<MB, 256>>>(x, W1l, nullptr, pY);
    aggregate_kernel<<<WB, 256>>>();
    gemm_conv<128, true><<<MB, 256>>>(x, W1r, b1l, pHA);

    // ---- layer 2: in = hA (K=64) ----
    gemm_conv<64, false><<<MB, 256>>>(pHA, W2l, nullptr, pY);
    aggregate_kernel<<<WB, 256>>>();
    gemm_conv<64, true><<<MB, 256>>>(pHA, W2r, b2l, pHB);

    // ---- layer 3: in = hB (K=64) ----
    gemm_conv<64, false><<<MB, 256>>>(pHB, W3l, nullptr, pY);
    aggregate_kernel<<<WB, 256>>>();
    gemm_conv<64, true><<<MB, 256>>>(pHB, W3r, b3l, pHA);

    // ---- global mean pool ----
    zero_pool_kernel<<<(NG * H + 255) / 256, 256>>>();
    pool_kernel<<<WB, 256>>>();
    poolnorm_kernel<<<(NG * H + 255) / 256, 256>>>();

    // ---- MLP head ----
    {
        dim3 grid1((256 + 127) / 128, NG);
        gemm_small<<<grid1, 128>>>(pPool, lin1_w, lin1_b, pT1, 256, 64);
        bn_tanh_kernel<<<256, 256>>>(pT1, g1, be1, 256);

        dim3 grid2((128 + 127) / 128, NG);
        gemm_small<<<grid2, 128>>>(pT1, lin2_w, lin2_b, pT2, 128, 256);
        bn_tanh_kernel<<<128, 256>>>(pT2, g2, be2, 128);

        dim3 grid3((64 + 63) / 64, NG);
        gemm_small<<<grid3, 64>>>(pT2, lin3_w, lin3_b, pT3, 64, 128);
        bn_tanh_kernel<<<64, 256>>>(pT3, g3, be3, 64);

        dim3 grid4(1, NG);
        gemm_small<<<grid4, 32>>>(pT3, lin4_w, lin4_b, out, 10, 64);
    }
}